// round 6
// baseline (speedup 1.0000x reference)
#include <cuda_runtime.h>
#include <cuda_bf16.h>
#include <cstdint>

// Problem constants
#define BB 64
#define PP 196
#define EE 2048
#define LL 32
#define VV 10000
#define EMB 512
#define DEC 512
#define ATT 512
#define TT 31   // L-1 steps
#define NBLK 148

// ---------------- device scratch ----------------
__device__ __align__(16) int   d_sort_src[BB];
__device__ __align__(16) int   d_nb[TT + 1];
__device__ int   d_total;
__device__ __align__(16) int   d_rowmap[BB * TT];
__device__ __align__(16) float d_mean[BB * EE];
__device__ __align__(16) float d_h[BB * DEC];
__device__ __align__(16) float d_c[BB * DEC];
__device__ __align__(16) float d_hhist[(size_t)TT * BB * DEC];
__device__ __align__(16) float d_att1[(size_t)BB * PP * ATT];
__device__ __align__(16) float d_att2[BB * ATT];
__device__ __align__(16) float d_gate[BB * EE];
__device__ __align__(16) float d_xbuf[BB * 3072];  // [emb(512) | gate*awe(2048) | h(512)]
__device__ __align__(16) float d_part[8 * BB * 2048];

// grid barrier state
__device__ volatile unsigned d_bar_gen;
__device__ unsigned d_bar_count;

#define BUF_MEAN 0
#define BUF_H    1
#define BUF_C    2

__device__ __forceinline__ float* selbuf(int s) {
    switch (s) {
        case BUF_MEAN: return d_mean;
        case BUF_H:    return d_h;
        case BUF_C:    return d_c;
        default:       return nullptr;
    }
}

// ---------------- setup: argsort, nb counts, compact row map ----------------
__global__ void k_setup(const int* __restrict__ cap_len) {
    __shared__ int lens[BB];
    __shared__ int nbs[TT + 1];
    __shared__ int off[TT + 1];
    int b = threadIdx.x;
    if (b < BB) lens[b] = cap_len[b];
    __syncthreads();
    if (b < BB) {
        int rank = 0;
        int lb = lens[b];
        for (int j = 0; j < BB; j++) {
            int lj = lens[j];
            if (lj > lb || (lj == lb && j < b)) rank++;
        }
        d_sort_src[rank] = b;
    }
    if (b <= TT) {
        int cnt = 0;
        for (int j = 0; j < BB; j++) if (lens[j] - 1 > b) cnt++;
        d_nb[b] = cnt;
        nbs[b] = cnt;
    }
    __syncthreads();
    if (b == 0) {
        int a = 0;
        for (int t = 0; t < TT; t++) { off[t] = a; a += nbs[t]; }
        d_total = a;
    }
    __syncthreads();
    if (b < BB) {
        for (int t = 0; t < TT; t++)
            if (b < nbs[t]) d_rowmap[off[t] + b] = (t << 6) | b;
    }
}

__global__ void k_zero(float* __restrict__ out, size_t n) {
    size_t i = (size_t)blockIdx.x * blockDim.x + threadIdx.x;
    size_t stride = (size_t)gridDim.x * blockDim.x;
    for (; i < n; i += stride) out[i] = 0.0f;
}

__global__ void k_mean(const float* __restrict__ enc) {
    int b = blockIdx.y;
    int e = blockIdx.x * 256 + threadIdx.x;
    const float* base = enc + (size_t)d_sort_src[b] * PP * EE + e;
    float s = 0.0f;
    #pragma unroll 7
    for (int p = 0; p < PP; p++) s += base[(size_t)p * EE];
    d_mean[b * EE + e] = s * (1.0f / 196.0f);
}

// ---------------- W element load (row-concat) ----------------
__device__ __forceinline__ float wload(const float* __restrict__ W1, const float* __restrict__ W2,
                                       int K1, int Nw, int kg, int n) {
    if (W2 != nullptr && kg >= K1) return W2[(size_t)(kg - K1) * Nw + n];
    return W1[(size_t)kg * Nw + n];
}

// ---------------- generic split-K GEMM into d_part (pre-loop h0/c0) ----------------
__global__ void k_gemm(int xsel,
                       const float* __restrict__ W1,
                       int K, int N, int S) {
    __shared__ __align__(16) float Xs[2][16][68];
    __shared__ __align__(16) float Ws[2][16][34];

    const float* X = selbuf(xsel);
    int tid = threadIdx.x;
    int n0 = blockIdx.x * 32;

    int s = blockIdx.y;
    int kbeg = s * (K / S);
    int ntiles = (K / S) / 16;

    int nl = tid & 15;
    int mg = tid >> 4;
    int m0 = mg << 2;

    int lm = tid >> 2, lk = (tid & 3) << 2;
    int wk = tid >> 4, wn = tid & 15;
    const float* Xrow = X + (size_t)lm * K;

    float acc[4][2];
    #pragma unroll
    for (int i = 0; i < 4; i++) { acc[i][0] = 0.f; acc[i][1] = 0.f; }

    float4 xr; float wr0, wr1;
    {
        int k0 = kbeg;
        xr = *reinterpret_cast<const float4*>(Xrow + k0 + lk);
        int kg = k0 + wk;
        wr0 = W1[(size_t)kg * N + n0 + wn];
        wr1 = W1[(size_t)kg * N + n0 + wn + 16];
    }
    Xs[0][lk + 0][lm] = xr.x; Xs[0][lk + 1][lm] = xr.y;
    Xs[0][lk + 2][lm] = xr.z; Xs[0][lk + 3][lm] = xr.w;
    Ws[0][wk][wn] = wr0; Ws[0][wk][wn + 16] = wr1;
    __syncthreads();

    for (int it = 0; it < ntiles; it++) {
        int cur = it & 1;
        bool more = (it + 1 < ntiles);
        if (more) {
            int k0 = kbeg + (it + 1) * 16;
            xr = *reinterpret_cast<const float4*>(Xrow + k0 + lk);
            int kg = k0 + wk;
            wr0 = W1[(size_t)kg * N + n0 + wn];
            wr1 = W1[(size_t)kg * N + n0 + wn + 16];
        }
        #pragma unroll
        for (int kk = 0; kk < 16; kk++) {
            float4 xv = *reinterpret_cast<const float4*>(&Xs[cur][kk][m0]);
            float2 wv = *reinterpret_cast<const float2*>(&Ws[cur][kk][nl * 2]);
            acc[0][0] += xv.x * wv.x; acc[0][1] += xv.x * wv.y;
            acc[1][0] += xv.y * wv.x; acc[1][1] += xv.y * wv.y;
            acc[2][0] += xv.z * wv.x; acc[2][1] += xv.z * wv.y;
            acc[3][0] += xv.w * wv.x; acc[3][1] += xv.w * wv.y;
        }
        if (more) {
            int nxt = cur ^ 1;
            Xs[nxt][lk + 0][lm] = xr.x; Xs[nxt][lk + 1][lm] = xr.y;
            Xs[nxt][lk + 2][lm] = xr.z; Xs[nxt][lk + 3][lm] = xr.w;
            Ws[nxt][wk][wn] = wr0; Ws[nxt][wk][wn + 16] = wr1;
        }
        __syncthreads();
    }

    int na = n0 + nl * 2;
    #pragma unroll
    for (int j = 0; j < 4; j++) {
        int m = m0 + j;
        size_t base = ((size_t)(s * BB + m)) * N + na;
        d_part[base] = acc[j][0];
        d_part[base + 1] = acc[j][1];
    }
}

__global__ void k_reduce(int N, int S, const float* __restrict__ b1, int ysel) {
    int idx = blockIdx.x * 256 + threadIdx.x;
    if (idx >= BB * N) return;
    int m = idx / N, n = idx - m * N;
    float v = b1 ? b1[n] : 0.f;
    for (int s = 0; s < S; s++) v += d_part[((size_t)(s * BB + m)) * N + n];
    selbuf(ysel)[(size_t)m * N + n] = v;
}

// ---------------- att1 = enc[sorted] @ We + be, double-buffered ----------------
__global__ void __launch_bounds__(256, 2) k_att1(const float* __restrict__ enc,
                                                 const float* __restrict__ We,
                                                 const float* __restrict__ be) {
    __shared__ __align__(16) float As[2][16][136];
    __shared__ __align__(16) float Bs[2][16][68];
    int tid = threadIdx.x;
    int tn = tid & 15, tm = tid >> 4;
    int n0l = tn * 4;
    int m0l = tm * 8;
    int rowBase = blockIdx.x * 128;
    int colBase = blockIdx.y * 64;

    int lm = tid >> 1;
    int lk = (tid & 1) << 3;
    int r = rowBase + lm;
    int bidx = r / PP, pidx = r % PP;
    const float* Arow = enc + ((size_t)d_sort_src[bidx] * PP + pidx) * EE;

    int bk = tid >> 4, bn = (tid & 15) << 2;

    float acc[8][4];
    #pragma unroll
    for (int i = 0; i < 8; i++)
        #pragma unroll
        for (int j = 0; j < 4; j++) acc[i][j] = 0.f;

    float4 av0, av1, bv;
    av0 = *reinterpret_cast<const float4*>(Arow + lk);
    av1 = *reinterpret_cast<const float4*>(Arow + lk + 4);
    bv  = *reinterpret_cast<const float4*>(We + (size_t)bk * ATT + colBase + bn);
    As[0][lk + 0][lm] = av0.x; As[0][lk + 1][lm] = av0.y;
    As[0][lk + 2][lm] = av0.z; As[0][lk + 3][lm] = av0.w;
    As[0][lk + 4][lm] = av1.x; As[0][lk + 5][lm] = av1.y;
    As[0][lk + 6][lm] = av1.z; As[0][lk + 7][lm] = av1.w;
    *reinterpret_cast<float4*>(&Bs[0][bk][bn]) = bv;
    __syncthreads();

    const int ntiles = EE / 16;  // 128
    for (int it = 0; it < ntiles; it++) {
        int cur = it & 1;
        bool more = (it + 1 < ntiles);
        if (more) {
            int k0 = (it + 1) * 16;
            av0 = *reinterpret_cast<const float4*>(Arow + k0 + lk);
            av1 = *reinterpret_cast<const float4*>(Arow + k0 + lk + 4);
            bv  = *reinterpret_cast<const float4*>(We + (size_t)(k0 + bk) * ATT + colBase + bn);
        }
        #pragma unroll
        for (int kk = 0; kk < 16; kk++) {
            float4 x0 = *reinterpret_cast<const float4*>(&As[cur][kk][m0l]);
            float4 x1 = *reinterpret_cast<const float4*>(&As[cur][kk][m0l + 4]);
            float4 w  = *reinterpret_cast<const float4*>(&Bs[cur][kk][n0l]);
            float xr[8] = {x0.x, x0.y, x0.z, x0.w, x1.x, x1.y, x1.z, x1.w};
            float wr[4] = {w.x, w.y, w.z, w.w};
            #pragma unroll
            for (int i = 0; i < 8; i++)
                #pragma unroll
                for (int j = 0; j < 4; j++)
                    acc[i][j] += xr[i] * wr[j];
        }
        if (more) {
            int nxt = cur ^ 1;
            As[nxt][lk + 0][lm] = av0.x; As[nxt][lk + 1][lm] = av0.y;
            As[nxt][lk + 2][lm] = av0.z; As[nxt][lk + 3][lm] = av0.w;
            As[nxt][lk + 4][lm] = av1.x; As[nxt][lk + 5][lm] = av1.y;
            As[nxt][lk + 6][lm] = av1.z; As[nxt][lk + 7][lm] = av1.w;
            *reinterpret_cast<float4*>(&Bs[nxt][bk][bn]) = bv;
        }
        __syncthreads();
    }

    int c = colBase + n0l;
    #pragma unroll
    for (int i = 0; i < 8; i++) {
        int rr = rowBase + m0l + i;
        float4 o;
        o.x = acc[i][0] + be[c + 0];
        o.y = acc[i][1] + be[c + 1];
        o.z = acc[i][2] + be[c + 2];
        o.w = acc[i][3] + be[c + 3];
        *reinterpret_cast<float4*>(d_att1 + (size_t)rr * ATT + c) = o;
    }
}

// ================= persistent loop kernel =================
struct SmG { float Xs[2][16][68]; float Ws[2][16][34]; };
struct SmA { float a2[ATT]; float wf[ATT]; float es[200]; float red[8]; float redsum[8]; };
union SmU { SmG g; SmA a; };

__device__ __forceinline__ void grid_barrier() {
    __syncthreads();
    if (threadIdx.x == 0) {
        unsigned gen = d_bar_gen;
        __threadfence();
        unsigned tkt = atomicAdd(&d_bar_count, 1u);
        if (tkt == NBLK - 1) {
            d_bar_count = 0;
            __threadfence();
            d_bar_gen = gen + 1;
        } else {
            while (d_bar_gen == gen) {}
        }
        __threadfence();
    }
    __syncthreads();
}

// phase A: att2 = h@Wd+bd (tiles 0..15), gate = sigmoid(h@Wb+bb) (tiles 16..79)
__device__ void phaseA(SmU* sm, const float* __restrict__ Wd, const float* __restrict__ bd,
                       const float* __restrict__ Wb, const float* __restrict__ bb, int t) {
    int bx = blockIdx.x;
    if (bx >= 80) return;
    int nb = d_nb[t];
    const float* W; const float* bias; float* Y;
    int Nw, act, n0;
    if (bx < 16) { W = Wd; bias = bd; Y = d_att2; Nw = ATT; act = 0; n0 = bx * 32; }
    else         { W = Wb; bias = bb; Y = d_gate; Nw = EE;  act = 1; n0 = (bx - 16) * 32; }

    int tid = threadIdx.x;
    int nl = tid & 15;
    int mg = tid >> 4;
    int m0 = mg << 2;
    bool rowact = (m0 < nb);

    int lm = tid >> 2, lk = (tid & 3) << 2;
    int wk = tid >> 4, wn = tid & 15;
    const float* Xrow = d_h + (size_t)lm * DEC;

    float acc[4][2];
    #pragma unroll
    for (int i = 0; i < 4; i++) { acc[i][0] = 0.f; acc[i][1] = 0.f; }

    float4 xr; float wr0, wr1;
    xr = *reinterpret_cast<const float4*>(Xrow + lk);
    wr0 = W[(size_t)wk * Nw + n0 + wn];
    wr1 = W[(size_t)wk * Nw + n0 + wn + 16];
    sm->g.Xs[0][lk + 0][lm] = xr.x; sm->g.Xs[0][lk + 1][lm] = xr.y;
    sm->g.Xs[0][lk + 2][lm] = xr.z; sm->g.Xs[0][lk + 3][lm] = xr.w;
    sm->g.Ws[0][wk][wn] = wr0; sm->g.Ws[0][wk][wn + 16] = wr1;
    __syncthreads();

    const int ntiles = DEC / 16;  // 32
    for (int it = 0; it < ntiles; it++) {
        int cur = it & 1;
        bool more = (it + 1 < ntiles);
        if (more) {
            int k0 = (it + 1) * 16;
            xr = *reinterpret_cast<const float4*>(Xrow + k0 + lk);
            int kg = k0 + wk;
            wr0 = W[(size_t)kg * Nw + n0 + wn];
            wr1 = W[(size_t)kg * Nw + n0 + wn + 16];
        }
        if (rowact) {
            #pragma unroll
            for (int kk = 0; kk < 16; kk++) {
                float4 xv = *reinterpret_cast<const float4*>(&sm->g.Xs[cur][kk][m0]);
                float2 wv = *reinterpret_cast<const float2*>(&sm->g.Ws[cur][kk][nl * 2]);
                acc[0][0] += xv.x * wv.x; acc[0][1] += xv.x * wv.y;
                acc[1][0] += xv.y * wv.x; acc[1][1] += xv.y * wv.y;
                acc[2][0] += xv.z * wv.x; acc[2][1] += xv.z * wv.y;
                acc[3][0] += xv.w * wv.x; acc[3][1] += xv.w * wv.y;
            }
        }
        if (more) {
            int nxt = cur ^ 1;
            sm->g.Xs[nxt][lk + 0][lm] = xr.x; sm->g.Xs[nxt][lk + 1][lm] = xr.y;
            sm->g.Xs[nxt][lk + 2][lm] = xr.z; sm->g.Xs[nxt][lk + 3][lm] = xr.w;
            sm->g.Ws[nxt][wk][wn] = wr0; sm->g.Ws[nxt][wk][wn + 16] = wr1;
        }
        __syncthreads();
    }

    if (rowact) {
        int na = n0 + nl * 2;
        float b0v = bias[na], b1v = bias[na + 1];
        #pragma unroll
        for (int j = 0; j < 4; j++) {
            int m = m0 + j;
            if (m < nb) {
                float v0 = acc[j][0] + b0v;
                float v1 = acc[j][1] + b1v;
                if (act == 1) {
                    v0 = 1.0f / (1.0f + __expf(-v0));
                    v1 = 1.0f / (1.0f + __expf(-v1));
                }
                Y[(size_t)m * Nw + na] = v0;
                Y[(size_t)m * Nw + na + 1] = v1;
            }
        }
    }
}

// phase B: e -> softmax -> awe -> xbuf (blocks 0..nb-1), 256 threads
__device__ void phaseB(SmU* sm, const float* __restrict__ enc, const int* __restrict__ caps,
                       const float* __restrict__ emb,
                       const float* __restrict__ Wf, const float* __restrict__ bf,
                       float* __restrict__ out_alphas, int t) {
    int b = blockIdx.x;
    if (b >= 64 || b >= d_nb[t]) return;
    int tid = threadIdx.x;
    sm->a.a2[tid]       = d_att2[b * ATT + tid];
    sm->a.a2[tid + 256] = d_att2[b * ATT + 256 + tid];
    sm->a.wf[tid]       = Wf[tid];
    sm->a.wf[tid + 256] = Wf[tid + 256];
    __syncthreads();
    int lane = tid & 31, warp = tid >> 5;

    const float4* a24 = reinterpret_cast<const float4*>(sm->a.a2);
    const float4* wf4 = reinterpret_cast<const float4*>(sm->a.wf);
    for (int p = warp; p < PP; p += 8) {
        const float4* row4 = reinterpret_cast<const float4*>(d_att1 + ((size_t)b * PP + p) * ATT);
        float s = 0.f;
        #pragma unroll
        for (int i = 0; i < 4; i++) {
            int idx = lane + i * 32;
            float4 v = row4[idx];
            float4 a = a24[idx];
            float4 w = wf4[idx];
            s += fmaxf(v.x + a.x, 0.f) * w.x;
            s += fmaxf(v.y + a.y, 0.f) * w.y;
            s += fmaxf(v.z + a.z, 0.f) * w.z;
            s += fmaxf(v.w + a.w, 0.f) * w.w;
        }
        #pragma unroll
        for (int off = 16; off > 0; off >>= 1) s += __shfl_xor_sync(0xffffffffu, s, off);
        if (lane == 0) sm->a.es[p] = s + bf[0];
    }
    __syncthreads();

    float v = (tid < PP) ? sm->a.es[tid] : -1e30f;
    float m = v;
    #pragma unroll
    for (int off = 16; off > 0; off >>= 1) m = fmaxf(m, __shfl_xor_sync(0xffffffffu, m, off));
    if (lane == 0) sm->a.red[warp] = m;
    __syncthreads();
    if (tid == 0) {
        float mm = sm->a.red[0];
        for (int i = 1; i < 8; i++) mm = fmaxf(mm, sm->a.red[i]);
        sm->a.red[0] = mm;
    }
    __syncthreads();
    float smax = sm->a.red[0];
    float ev = (tid < PP) ? __expf(v - smax) : 0.f;
    float s = ev;
    #pragma unroll
    for (int off = 16; off > 0; off >>= 1) s += __shfl_xor_sync(0xffffffffu, s, off);
    if (lane == 0) sm->a.redsum[warp] = s;
    __syncthreads();
    if (tid == 0) {
        float ss = sm->a.redsum[0];
        for (int i = 1; i < 8; i++) ss += sm->a.redsum[i];
        sm->a.redsum[0] = ss;
    }
    __syncthreads();
    float inv = 1.0f / sm->a.redsum[0];
    float al = ev * inv;
    if (tid < PP) {
        sm->a.es[tid] = al;
        out_alphas[((size_t)b * TT + t) * PP + tid] = al;
    }
    __syncthreads();

    // awe: float4 lanes 0..511; each thread handles tid and tid+256
    int src = d_sort_src[b];
    const float4* enc4 = reinterpret_cast<const float4*>(enc + (size_t)src * PP * EE);
    float4 acc0 = make_float4(0.f, 0.f, 0.f, 0.f);
    float4 acc1 = make_float4(0.f, 0.f, 0.f, 0.f);
    #pragma unroll 4
    for (int p = 0; p < PP; p++) {
        float alp = sm->a.es[p];
        float4 e0 = enc4[p * 512 + tid];
        float4 e1 = enc4[p * 512 + tid + 256];
        acc0.x += alp * e0.x; acc0.y += alp * e0.y; acc0.z += alp * e0.z; acc0.w += alp * e0.w;
        acc1.x += alp * e1.x; acc1.y += alp * e1.y; acc1.z += alp * e1.z; acc1.w += alp * e1.w;
    }
    const float4* g4 = reinterpret_cast<const float4*>(d_gate + (size_t)b * EE);
    float4 ga = g4[tid], gb = g4[tid + 256];
    float4* xb4 = reinterpret_cast<float4*>(d_xbuf + (size_t)b * 3072);
    xb4[128 + tid]       = make_float4(acc0.x * ga.x, acc0.y * ga.y, acc0.z * ga.z, acc0.w * ga.w);
    xb4[128 + tid + 256] = make_float4(acc1.x * gb.x, acc1.y * gb.y, acc1.z * gb.z, acc1.w * gb.w);

    if (tid < 128) {
        int cap = caps[src * LL + t];
        const float4* emb4 = reinterpret_cast<const float4*>(emb + (size_t)cap * EMB);
        xb4[tid] = emb4[tid];
        xb4[640 + tid] = reinterpret_cast<const float4*>(d_h + (size_t)b * DEC)[tid];
    }
}

// phase C: g partials = xbuf @ [Wih;Whh], split-K 2 (tasks 0..127)
__device__ void phaseC(SmU* sm, const float* __restrict__ Wih, const float* __restrict__ Whh, int t) {
    int bx = blockIdx.x;
    if (bx >= 128) return;
    int nb = d_nb[t];
    int n0 = (bx & 63) * 32;
    int s = bx >> 6;
    const int K = 3072, K1 = 2560, N = 2048;
    int kbeg = s * 1536;
    const int ntiles = 96;

    int tid = threadIdx.x;
    int nl = tid & 15;
    int mg = tid >> 4;
    int m0 = mg << 2;
    bool rowact = (m0 < nb);

    int lm = tid >> 2, lk = (tid & 3) << 2;
    int wk = tid >> 4, wn = tid & 15;
    const float* Xrow = d_xbuf + (size_t)lm * K;

    float acc[4][2];
    #pragma unroll
    for (int i = 0; i < 4; i++) { acc[i][0] = 0.f; acc[i][1] = 0.f; }

    float4 xr; float wr0, wr1;
    {
        int k0 = kbeg;
        xr = *reinterpret_cast<const float4*>(Xrow + k0 + lk);
        int kg = k0 + wk;
        wr0 = wload(Wih, Whh, K1, N, kg, n0 + wn);
        wr1 = wload(Wih, Whh, K1, N, kg, n0 + wn + 16);
    }
    sm->g.Xs[0][lk + 0][lm] = xr.x; sm->g.Xs[0][lk + 1][lm] = xr.y;
    sm->g.Xs[0][lk + 2][lm] = xr.z; sm->g.Xs[0][lk + 3][lm] = xr.w;
    sm->g.Ws[0][wk][wn] = wr0; sm->g.Ws[0][wk][wn + 16] = wr1;
    __syncthreads();

    for (int it = 0; it < ntiles; it++) {
        int cur = it & 1;
        bool more = (it + 1 < ntiles);
        if (more) {
            int k0 = kbeg + (it + 1) * 16;
            xr = *reinterpret_cast<const float4*>(Xrow + k0 + lk);
            int kg = k0 + wk;
            wr0 = wload(Wih, Whh, K1, N, kg, n0 + wn);
            wr1 = wload(Wih, Whh, K1, N, kg, n0 + wn + 16);
        }
        if (rowact) {
            #pragma unroll
            for (int kk = 0; kk < 16; kk++) {
                float4 xv = *reinterpret_cast<const float4*>(&sm->g.Xs[cur][kk][m0]);
                float2 wv = *reinterpret_cast<const float2*>(&sm->g.Ws[cur][kk][nl * 2]);
                acc[0][0] += xv.x * wv.x; acc[0][1] += xv.x * wv.y;
                acc[1][0] += xv.y * wv.x; acc[1][1] += xv.y * wv.y;
                acc[2][0] += xv.z * wv.x; acc[2][1] += xv.z * wv.y;
                acc[3][0] += xv.w * wv.x; acc[3][1] += xv.w * wv.y;
            }
        }
        if (more) {
            int nxt = cur ^ 1;
            sm->g.Xs[nxt][lk + 0][lm] = xr.x; sm->g.Xs[nxt][lk + 1][lm] = xr.y;
            sm->g.Xs[nxt][lk + 2][lm] = xr.z; sm->g.Xs[nxt][lk + 3][lm] = xr.w;
            sm->g.Ws[nxt][wk][wn] = wr0; sm->g.Ws[nxt][wk][wn + 16] = wr1;
        }
        __syncthreads();
    }

    if (rowact) {
        int na = n0 + nl * 2;
        #pragma unroll
        for (int j = 0; j < 4; j++) {
            int m = m0 + j;
            if (m < nb) {
                size_t base = ((size_t)(s * BB + m)) * N + na;
                d_part[base] = acc[j][0];
                d_part[base + 1] = acc[j][1];
            }
        }
    }
}

// phase D: reduce S=2 partials + biases + LSTM pointwise -> h, c, hhist
__device__ void phaseD(const float* __restrict__ bih, const float* __restrict__ bhh, int t) {
    if (blockIdx.x >= 128) return;
    int idx = blockIdx.x * 256 + threadIdx.x;
    int b = idx >> 9, d = idx & 511;
    if (b >= d_nb[t]) return;
    float gi = bih[d] + bhh[d];
    float gf = bih[512 + d] + bhh[512 + d];
    float gg = bih[1024 + d] + bhh[1024 + d];
    float go = bih[1536 + d] + bhh[1536 + d];
    #pragma unroll
    for (int s = 0; s < 2; s++) {
        const float* p = d_part + ((size_t)(s * BB + b)) * 2048;
        gi += p[d]; gf += p[512 + d]; gg += p[1024 + d]; go += p[1536 + d];
    }
    float c = d_c[b * DEC + d];
    float si = 1.0f / (1.0f + __expf(-gi));
    float sf = 1.0f / (1.0f + __expf(-gf));
    float so = 1.0f / (1.0f + __expf(-go));
    float cn = sf * c + si * tanhf(gg);
    float hn = so * tanhf(cn);
    d_c[b * DEC + d] = cn;
    d_h[b * DEC + d] = hn;
    d_hhist[((size_t)t * BB + b) * DEC + d] = hn;
}

__global__ void __launch_bounds__(256, 1) k_loop(
        const float* __restrict__ enc, const int* __restrict__ caps,
        const float* __restrict__ emb,
        const float* __restrict__ Wd, const float* __restrict__ bd,
        const float* __restrict__ Wb, const float* __restrict__ bb,
        const float* __restrict__ Wf, const float* __restrict__ bf,
        const float* __restrict__ Wih, const float* __restrict__ bih,
        const float* __restrict__ Whh, const float* __restrict__ bhh,
        float* __restrict__ out_alphas) {
    __shared__ __align__(16) SmU sm;
    for (int t = 0; t < TT; t++) {
        phaseA(&sm, Wd, bd, Wb, bb, t);
        grid_barrier();
        phaseB(&sm, enc, caps, emb, Wf, bf, out_alphas, t);
        grid_barrier();
        phaseC(&sm, Wih, Whh, t);
        grid_barrier();
        phaseD(bih, bhh, t);
        grid_barrier();
    }
}

// ---------------- batched preds: compact rows @ Wfc, 128x64 tile ----------------
__global__ void __launch_bounds__(256, 2) k_preds(const float* __restrict__ Wfc,
                                                  const float* __restrict__ bfc,
                                                  float* __restrict__ out) {
    int total = d_total;
    int rowBase = blockIdx.x * 128;
    if (rowBase >= total) return;
    int colBase = blockIdx.y * 64;

    __shared__ __align__(16) float As[2][16][136];
    __shared__ __align__(16) float Bs[2][16][68];
    int tid = threadIdx.x;
    int tn = tid & 15, tm = tid >> 4;
    int n0l = tn * 4;
    int m0l = tm * 8;

    int lm = tid >> 1;
    int lk = (tid & 1) << 3;
    int r = rowBase + lm;
    bool rvalid = (r < total);
    const float* Arow = d_hhist + (size_t)(rvalid ? d_rowmap[r] : 0) * DEC;

    int bk = tid >> 4, bn = (tid & 15) << 2;
    int bcol = colBase + bn;
    bool cvalid = (bcol < VV);

    float acc[8][4];
    #pragma unroll
    for (int i = 0; i < 8; i++)
        #pragma unroll
        for (int j = 0; j < 4; j++) acc[i][j] = 0.f;

    float4 av0, av1, bv;
    auto loadA = [&](int k0) {
        if (rvalid) {
            av0 = *reinterpret_cast<const float4*>(Arow + k0 + lk);
            av1 = *reinterpret_cast<const float4*>(Arow + k0 + lk + 4);
        } else {
            av0 = make_float4(0.f, 0.f, 0.f, 0.f);
            av1 = av0;
        }
    };
    auto loadB = [&](int k0) {
        if (cvalid) bv = *reinterpret_cast<const float4*>(Wfc + (size_t)(k0 + bk) * VV + bcol);
        else        bv = make_float4(0.f, 0.f, 0.f, 0.f);
    };

    loadA(0); loadB(0);
    As[0][lk + 0][lm] = av0.x; As[0][lk + 1][lm] = av0.y;
    As[0][lk + 2][lm] = av0.z; As[0][lk + 3][lm] = av0.w;
    As[0][lk + 4][lm] = av1.x; As[0][lk + 5][lm] = av1.y;
    As[0][lk + 6][lm] = av1.z; As[0][lk + 7][lm] = av1.w;
    *reinterpret_cast<float4*>(&Bs[0][bk][bn]) = bv;
    __syncthreads();

    const int ntiles = DEC / 16;  // 32
    for (int it = 0; it < ntiles; it++) {
        int cur = it & 1;
        bool more = (it + 1 < ntiles);
        if (more) { loadA((it + 1) * 16); loadB((it + 1) * 16); }
        #pragma unroll
        for (int kk = 0; kk < 16; kk++) {
            float4 x0 = *reinterpret_cast<const float4*>(&As[cur][kk][m0l]);
            float4 x1 = *reinterpret_cast<const float4*>(&As[cur][kk][m0l + 4]);
            float4 w  = *reinterpret_cast<const float4*>(&Bs[cur][kk][n0l]);
            float xr[8] = {x0.x, x0.y, x0.z, x0.w, x1.x, x1.y, x1.z, x1.w};
            float wr[4] = {w.x, w.y, w.z, w.w};
            #pragma unroll
            for (int i = 0; i < 8; i++)
                #pragma unroll
                for (int j = 0; j < 4; j++)
                    acc[i][j] += xr[i] * wr[j];
        }
        if (more) {
            int nxt = cur ^ 1;
            As[nxt][lk + 0][lm] = av0.x; As[nxt][lk + 1][lm] = av0.y;
            As[nxt][lk + 2][lm] = av0.z; As[nxt][lk + 3][lm] = av0.w;
            As[nxt][lk + 4][lm] = av1.x; As[nxt][lk + 5][lm] = av1.y;
            As[nxt][lk + 6][lm] = av1.z; As[nxt][lk + 7][lm] = av1.w;
            *reinterpret_cast<float4*>(&Bs[nxt][bk][bn]) = bv;
        }
        __syncthreads();
    }

    int c = colBase + n0l;
    #pragma unroll
    for (int i = 0; i < 8; i++) {
        int rr = rowBase + m0l + i;
        if (rr >= total) break;
        int mapped = d_rowmap[rr];
        int t = mapped >> 6, b = mapped & 63;
        float* orow = out + ((size_t)b * TT + t) * VV;
        #pragma unroll
        for (int j = 0; j < 4; j++) {
            int cc = c + j;
            if (cc < VV) orow[cc] = acc[i][j] + bfc[cc];
        }
    }
}

// ---------------- host launch ----------------
extern "C" void kernel_launch(void* const* d_in, const int* in_sizes, int n_in,
                              void* d_out, int out_size) {
    const float* enc  = (const float*)d_in[0];
    const int*   caps = (const int*)d_in[1];
    const int*   clen = (const int*)d_in[2];
    const float* emb  = (const float*)d_in[3];
    const float* We   = (const float*)d_in[4];
    const float* be   = (const float*)d_in[5];
    const float* Wd   = (const float*)d_in[6];
    const float* bd   = (const float*)d_in[7];
    const float* Wf   = (const float*)d_in[8];
    const float* bf   = (const float*)d_in[9];
    const float* Wih  = (const float*)d_in[10];
    const float* bih  = (const float*)d_in[11];
    const float* Whh  = (const float*)d_in[12];
    const float* bhh  = (const float*)d_in[13];
    const float* Wb   = (const float*)d_in[14];
    const float* bb   = (const float*)d_in[15];
    const float* Whi  = (const float*)d_in[16];
    const float* bhi  = (const float*)d_in[17];
    const float* Wci  = (const float*)d_in[18];
    const float* bci  = (const float*)d_in[19];
    const float* Wfc  = (const float*)d_in[20];
    const float* bfc  = (const float*)d_in[21];
    float* out = (float*)d_out;
    float* out_alphas = out + (size_t)BB * TT * VV;

    k_setup<<<1, 64>>>(clen);
    k_zero<<<2048, 256>>>(out, (size_t)out_size);
    k_mean<<<dim3(8, BB), 256>>>(enc);

    // h0 / c0 (split-K 8 over K=2048)
    k_gemm<<<dim3(16, 8), 256>>>(BUF_MEAN, Whi, EE, DEC, 8);
    k_reduce<<<128, 256>>>(DEC, 8, bhi, BUF_H);
    k_gemm<<<dim3(16, 8), 256>>>(BUF_MEAN, Wci, EE, DEC, 8);
    k_reduce<<<128, 256>>>(DEC, 8, bci, BUF_C);

    k_att1<<<dim3(98, 8), 256>>>(enc, We, be);

    // entire 31-step decode loop in ONE persistent kernel
    k_loop<<<NBLK, 256>>>(enc, caps, emb, Wd, bd, Wb, bb, Wf, bf,
                          Wih, bih, Whh, bhh, out_alphas);

    // batched vocab projection over all (t, b) active rows
    k_preds<<<dim3(16, 157), 256>>>(Wfc, bfc, out);
}

// round 7
// speedup vs baseline: 1.4045x; 1.4045x over previous
#include <cuda_runtime.h>
#include <cuda_bf16.h>
#include <cstdint>

// Problem constants
#define BB 64
#define PP 196
#define EE 2048
#define LL 32
#define VV 10000
#define EMB 512
#define DEC 512
#define ATT 512
#define TT 31   // L-1 steps

// ---------------- device scratch ----------------
__device__ __align__(16) int   d_sort_src[BB];
__device__ __align__(16) int   d_nb[TT + 1];
__device__ int   d_total;
__device__ __align__(16) int   d_rowmap[BB * TT];
__device__ __align__(16) float d_mean[BB * EE];
__device__ __align__(16) float d_h[BB * DEC];
__device__ __align__(16) float d_c[BB * DEC];
__device__ __align__(16) float d_hhist[(size_t)TT * BB * DEC];
__device__ __align__(16) float d_att1[(size_t)BB * PP * ATT];
__device__ __align__(16) float d_att2[BB * ATT];
__device__ __align__(16) float d_gate[BB * EE];
__device__ __align__(16) float d_xbuf[BB * 3072];
__device__ __align__(16) float d_part[8 * BB * 2048];

#define BUF_MEAN 0
#define BUF_H    1
#define BUF_C    2
#define BUF_XBUF 5

__device__ __forceinline__ float* selbuf(int s) {
    switch (s) {
        case BUF_MEAN: return d_mean;
        case BUF_H:    return d_h;
        case BUF_C:    return d_c;
        case BUF_XBUF: return d_xbuf;
        default:       return nullptr;
    }
}

// ---------------- tf32 helpers ----------------
__device__ __forceinline__ float tf32r(float f) {
    uint32_t u;
    asm("cvt.rna.tf32.f32 %0, %1;" : "=r"(u) : "f"(f));
    return __uint_as_float(u);
}
__device__ __forceinline__ void mma_tf32(float* c, const uint32_t* a, const uint32_t* b) {
    asm volatile("mma.sync.aligned.m16n8k8.row.col.f32.tf32.tf32.f32 "
        "{%0,%1,%2,%3}, {%4,%5,%6,%7}, {%8,%9}, {%0,%1,%2,%3};"
        : "+f"(c[0]), "+f"(c[1]), "+f"(c[2]), "+f"(c[3])
        : "r"(a[0]), "r"(a[1]), "r"(a[2]), "r"(a[3]), "r"(b[0]), "r"(b[1]));
}

// ---------------- setup: argsort, nb counts, compact row map ----------------
__global__ void k_setup(const int* __restrict__ cap_len) {
    __shared__ int lens[BB];
    __shared__ int nbs[TT + 1];
    __shared__ int off[TT + 1];
    int b = threadIdx.x;
    if (b < BB) lens[b] = cap_len[b];
    __syncthreads();
    if (b < BB) {
        int rank = 0;
        int lb = lens[b];
        for (int j = 0; j < BB; j++) {
            int lj = lens[j];
            if (lj > lb || (lj == lb && j < b)) rank++;
        }
        d_sort_src[rank] = b;
    }
    if (b <= TT) {
        int cnt = 0;
        for (int j = 0; j < BB; j++) if (lens[j] - 1 > b) cnt++;
        d_nb[b] = cnt;
        nbs[b] = cnt;
    }
    __syncthreads();
    if (b == 0) {
        int a = 0;
        for (int t = 0; t < TT; t++) { off[t] = a; a += nbs[t]; }
        d_total = a;
    }
    __syncthreads();
    if (b < BB) {
        for (int t = 0; t < TT; t++)
            if (b < nbs[t]) d_rowmap[off[t] + b] = (t << 6) | b;
    }
}

__global__ void k_zero(float* __restrict__ out, size_t n) {
    size_t i = (size_t)blockIdx.x * blockDim.x + threadIdx.x;
    size_t stride = (size_t)gridDim.x * blockDim.x;
    for (; i < n; i += stride) out[i] = 0.0f;
}

__global__ void k_mean(const float* __restrict__ enc) {
    int b = blockIdx.y;
    int e = blockIdx.x * 256 + threadIdx.x;
    const float* base = enc + (size_t)d_sort_src[b] * PP * EE + e;
    float s = 0.0f;
    #pragma unroll 7
    for (int p = 0; p < PP; p++) s += base[(size_t)p * EE];
    d_mean[b * EE + e] = s * (1.0f / 196.0f);
}

// ---------------- W element load (row-concat) ----------------
__device__ __forceinline__ float wload(const float* __restrict__ W1, const float* __restrict__ W2,
                                       int K1, int Nw, int kg, int n) {
    if (W2 != nullptr && kg >= K1) return W2[(size_t)(kg - K1) * Nw + n];
    return W1[(size_t)kg * Nw + n];
}

// ---------------- split-K GEMM into d_part (R5 version) ----------------
__global__ void k_gemm(int xsel,
                       const float* __restrict__ W1, const float* __restrict__ W2,
                       int K, int K1, int N, int t, int S) {
    __shared__ __align__(16) float Xs[2][16][68];
    __shared__ __align__(16) float Ws[2][16][34];

    const float* X = selbuf(xsel);
    int tid = threadIdx.x;
    int nb = (t >= 0) ? d_nb[t] : BB;
    int n0 = blockIdx.x * 32;

    int s = blockIdx.y;
    int kbeg = s * (K / S);
    int ntiles = (K / S) / 16;

    int nl = tid & 15;
    int mg = tid >> 4;
    int m0 = mg << 2;
    bool rowact = (m0 < nb);

    int lm = tid >> 2, lk = (tid & 3) << 2;
    int wk = tid >> 4, wn = tid & 15;
    const float* Xrow = X + (size_t)lm * K;

    float acc[4][2];
    #pragma unroll
    for (int i = 0; i < 4; i++) { acc[i][0] = 0.f; acc[i][1] = 0.f; }

    float4 xr; float wr0, wr1;
    {
        int k0 = kbeg;
        xr = *reinterpret_cast<const float4*>(Xrow + k0 + lk);
        int kg = k0 + wk;
        wr0 = wload(W1, W2, K1, N, kg, n0 + wn);
        wr1 = wload(W1, W2, K1, N, kg, n0 + wn + 16);
    }
    Xs[0][lk + 0][lm] = xr.x; Xs[0][lk + 1][lm] = xr.y;
    Xs[0][lk + 2][lm] = xr.z; Xs[0][lk + 3][lm] = xr.w;
    Ws[0][wk][wn] = wr0; Ws[0][wk][wn + 16] = wr1;
    __syncthreads();

    for (int it = 0; it < ntiles; it++) {
        int cur = it & 1;
        bool more = (it + 1 < ntiles);
        if (more) {
            int k0 = kbeg + (it + 1) * 16;
            xr = *reinterpret_cast<const float4*>(Xrow + k0 + lk);
            int kg = k0 + wk;
            wr0 = wload(W1, W2, K1, N, kg, n0 + wn);
            wr1 = wload(W1, W2, K1, N, kg, n0 + wn + 16);
        }
        if (rowact) {
            #pragma unroll
            for (int kk = 0; kk < 16; kk++) {
                float4 xv = *reinterpret_cast<const float4*>(&Xs[cur][kk][m0]);
                float2 wv = *reinterpret_cast<const float2*>(&Ws[cur][kk][nl * 2]);
                acc[0][0] += xv.x * wv.x; acc[0][1] += xv.x * wv.y;
                acc[1][0] += xv.y * wv.x; acc[1][1] += xv.y * wv.y;
                acc[2][0] += xv.z * wv.x; acc[2][1] += xv.z * wv.y;
                acc[3][0] += xv.w * wv.x; acc[3][1] += xv.w * wv.y;
            }
        }
        if (more) {
            int nxt = cur ^ 1;
            Xs[nxt][lk + 0][lm] = xr.x; Xs[nxt][lk + 1][lm] = xr.y;
            Xs[nxt][lk + 2][lm] = xr.z; Xs[nxt][lk + 3][lm] = xr.w;
            Ws[nxt][wk][wn] = wr0; Ws[nxt][wk][wn + 16] = wr1;
        }
        __syncthreads();
    }

    if (!rowact) return;
    int na = n0 + nl * 2;
    #pragma unroll
    for (int j = 0; j < 4; j++) {
        int m = m0 + j;
        if (m < nb) {
            size_t base = ((size_t)(s * BB + m)) * N + na;
            d_part[base] = acc[j][0];
            d_part[base + 1] = acc[j][1];
        }
    }
}

__global__ void k_reduce(int N, int S, const float* __restrict__ b1, int ysel, int t) {
    int idx = blockIdx.x * 256 + threadIdx.x;
    if (idx >= BB * N) return;
    int m = idx / N, n = idx - m * N;
    int nb = (t >= 0) ? d_nb[t] : BB;
    if (m >= nb) return;
    float v = b1 ? b1[n] : 0.f;
    for (int s = 0; s < S; s++) v += d_part[((size_t)(s * BB + m)) * N + n];
    selbuf(ysel)[(size_t)m * N + n] = v;
}

// ---------------- reduce g partials + fused LSTM pointwise + h history ----------------
__global__ void k_reduce_lstm(const float* __restrict__ bih, const float* __restrict__ bhh, int t) {
    int idx = blockIdx.x * 256 + threadIdx.x;
    int b = idx >> 9, d = idx & 511;
    if (b >= d_nb[t]) return;
    float gi = bih[d] + bhh[d];
    float gf = bih[512 + d] + bhh[512 + d];
    float gg = bih[1024 + d] + bhh[1024 + d];
    float go = bih[1536 + d] + bhh[1536 + d];
    #pragma unroll
    for (int s = 0; s < 4; s++) {
        const float* p = d_part + ((size_t)(s * BB + b)) * 2048;
        gi += p[d]; gf += p[512 + d]; gg += p[1024 + d]; go += p[1536 + d];
    }
    float c = d_c[b * DEC + d];
    float si = 1.0f / (1.0f + __expf(-gi));
    float sf = 1.0f / (1.0f + __expf(-gf));
    float so = 1.0f / (1.0f + __expf(-go));
    float cn = sf * c + si * tanhf(gg);
    float hn = so * tanhf(cn);
    d_c[b * DEC + d] = cn;
    d_h[b * DEC + d] = hn;
    d_hhist[((size_t)t * BB + b) * DEC + d] = hn;
}

// ---------------- fused att2(t) + gate(t): X = d_h, K = 512 ----------------
__global__ void __launch_bounds__(256, 2) k_ag(
        const float* __restrict__ Wd, const float* __restrict__ bd,
        const float* __restrict__ Wb, const float* __restrict__ bb, int t) {
    __shared__ __align__(16) float Xs[2][16][68];
    __shared__ __align__(16) float Ws[2][16][34];

    int bx = blockIdx.x;
    const float* W; const float* bias; float* Y;
    int Nw, act, n0;
    int nb = d_nb[t];
    if (bx < 16) { W = Wd; bias = bd; Y = d_att2; Nw = ATT; act = 0; n0 = bx * 32; }
    else         { W = Wb; bias = bb; Y = d_gate; Nw = EE;  act = 1; n0 = (bx - 16) * 32; }

    int tid = threadIdx.x;
    int nl = tid & 15;
    int mg = tid >> 4;
    int m0 = mg << 2;
    bool rowact = (m0 < nb);

    int lm = tid >> 2, lk = (tid & 3) << 2;
    int wk = tid >> 4, wn = tid & 15;
    const float* Xrow = d_h + (size_t)lm * DEC;

    float acc[4][2];
    #pragma unroll
    for (int i = 0; i < 4; i++) { acc[i][0] = 0.f; acc[i][1] = 0.f; }

    float4 xr; float wr0, wr1;
    xr = *reinterpret_cast<const float4*>(Xrow + lk);
    wr0 = W[(size_t)wk * Nw + n0 + wn];
    wr1 = W[(size_t)wk * Nw + n0 + wn + 16];
    Xs[0][lk + 0][lm] = xr.x; Xs[0][lk + 1][lm] = xr.y;
    Xs[0][lk + 2][lm] = xr.z; Xs[0][lk + 3][lm] = xr.w;
    Ws[0][wk][wn] = wr0; Ws[0][wk][wn + 16] = wr1;
    __syncthreads();

    const int ntiles = DEC / 16;  // 32
    for (int it = 0; it < ntiles; it++) {
        int cur = it & 1;
        bool more = (it + 1 < ntiles);
        if (more) {
            int k0 = (it + 1) * 16;
            xr = *reinterpret_cast<const float4*>(Xrow + k0 + lk);
            int kg = k0 + wk;
            wr0 = W[(size_t)kg * Nw + n0 + wn];
            wr1 = W[(size_t)kg * Nw + n0 + wn + 16];
        }
        if (rowact) {
            #pragma unroll
            for (int kk = 0; kk < 16; kk++) {
                float4 xv = *reinterpret_cast<const float4*>(&Xs[cur][kk][m0]);
                float2 wv = *reinterpret_cast<const float2*>(&Ws[cur][kk][nl * 2]);
                acc[0][0] += xv.x * wv.x; acc[0][1] += xv.x * wv.y;
                acc[1][0] += xv.y * wv.x; acc[1][1] += xv.y * wv.y;
                acc[2][0] += xv.z * wv.x; acc[2][1] += xv.z * wv.y;
                acc[3][0] += xv.w * wv.x; acc[3][1] += xv.w * wv.y;
            }
        }
        if (more) {
            int nxt = cur ^ 1;
            Xs[nxt][lk + 0][lm] = xr.x; Xs[nxt][lk + 1][lm] = xr.y;
            Xs[nxt][lk + 2][lm] = xr.z; Xs[nxt][lk + 3][lm] = xr.w;
            Ws[nxt][wk][wn] = wr0; Ws[nxt][wk][wn + 16] = wr1;
        }
        __syncthreads();
    }

    if (!rowact) return;
    int na = n0 + nl * 2;
    float b0v = bias[na], b1v = bias[na + 1];
    #pragma unroll
    for (int j = 0; j < 4; j++) {
        int m = m0 + j;
        if (m < nb) {
            float v0 = acc[j][0] + b0v;
            float v1 = acc[j][1] + b1v;
            if (act == 1) {
                v0 = 1.0f / (1.0f + __expf(-v0));
                v1 = 1.0f / (1.0f + __expf(-v1));
            }
            Y[(size_t)m * Nw + na] = v0;
            Y[(size_t)m * Nw + na + 1] = v1;
        }
    }
}

// ---------------- att1 = enc[sorted] @ We + be : tf32 MMA, 128x64 tile ----------------
__global__ void __launch_bounds__(256, 2) k_att1_mma(const float* __restrict__ enc,
                                                     const float* __restrict__ We,
                                                     const float* __restrict__ be) {
    __shared__ float As[2][16][136];  // [k][m], tf32-converted
    __shared__ float Bs[2][16][72];   // [k][n], tf32-converted
    int tid = threadIdx.x;
    int warp = tid >> 5, lane = tid & 31;
    int g = lane >> 2, tk = lane & 3;
    int mw = (warp & 3) * 32, nw = (warp >> 2) * 32;
    int rowBase = blockIdx.x * 128, colBase = blockIdx.y * 64;

    int lm = tid >> 1, lk = (tid & 1) << 3;
    int r = rowBase + lm;
    int bidx = r / PP, pidx = r % PP;
    const float* Arow = enc + ((size_t)d_sort_src[bidx] * PP + pidx) * EE;
    int bk = tid >> 4, bn = (tid & 15) << 2;

    float acc[2][4][4];
    #pragma unroll
    for (int i = 0; i < 2; i++)
        #pragma unroll
        for (int j = 0; j < 4; j++)
            #pragma unroll
            for (int q = 0; q < 4; q++) acc[i][j][q] = 0.f;

    float4 av0, av1, bv;
    av0 = *reinterpret_cast<const float4*>(Arow + lk);
    av1 = *reinterpret_cast<const float4*>(Arow + lk + 4);
    bv  = *reinterpret_cast<const float4*>(We + (size_t)bk * ATT + colBase + bn);
    As[0][lk + 0][lm] = tf32r(av0.x); As[0][lk + 1][lm] = tf32r(av0.y);
    As[0][lk + 2][lm] = tf32r(av0.z); As[0][lk + 3][lm] = tf32r(av0.w);
    As[0][lk + 4][lm] = tf32r(av1.x); As[0][lk + 5][lm] = tf32r(av1.y);
    As[0][lk + 6][lm] = tf32r(av1.z); As[0][lk + 7][lm] = tf32r(av1.w);
    *reinterpret_cast<float4*>(&Bs[0][bk][bn]) =
        make_float4(tf32r(bv.x), tf32r(bv.y), tf32r(bv.z), tf32r(bv.w));
    __syncthreads();

    const int ntiles = EE / 16;  // 128
    for (int it = 0; it < ntiles; it++) {
        int cur = it & 1;
        bool more = (it + 1 < ntiles);
        if (more) {
            int k0 = (it + 1) * 16;
            av0 = *reinterpret_cast<const float4*>(Arow + k0 + lk);
            av1 = *reinterpret_cast<const float4*>(Arow + k0 + lk + 4);
            bv  = *reinterpret_cast<const float4*>(We + (size_t)(k0 + bk) * ATT + colBase + bn);
        }
        #pragma unroll
        for (int ks = 0; ks < 16; ks += 8) {
            uint32_t a[2][4], bfr[4][2];
            #pragma unroll
            for (int i = 0; i < 2; i++) {
                a[i][0] = __float_as_uint(As[cur][ks + tk][mw + i * 16 + g]);
                a[i][1] = __float_as_uint(As[cur][ks + tk][mw + i * 16 + g + 8]);
                a[i][2] = __float_as_uint(As[cur][ks + tk + 4][mw + i * 16 + g]);
                a[i][3] = __float_as_uint(As[cur][ks + tk + 4][mw + i * 16 + g + 8]);
            }
            #pragma unroll
            for (int j = 0; j < 4; j++) {
                bfr[j][0] = __float_as_uint(Bs[cur][ks + tk][nw + j * 8 + g]);
                bfr[j][1] = __float_as_uint(Bs[cur][ks + tk + 4][nw + j * 8 + g]);
            }
            #pragma unroll
            for (int i = 0; i < 2; i++)
                #pragma unroll
                for (int j = 0; j < 4; j++)
                    mma_tf32(acc[i][j], a[i], bfr[j]);
        }
        if (more) {
            int nxt = cur ^ 1;
            As[nxt][lk + 0][lm] = tf32r(av0.x); As[nxt][lk + 1][lm] = tf32r(av0.y);
            As[nxt][lk + 2][lm] = tf32r(av0.z); As[nxt][lk + 3][lm] = tf32r(av0.w);
            As[nxt][lk + 4][lm] = tf32r(av1.x); As[nxt][lk + 5][lm] = tf32r(av1.y);
            As[nxt][lk + 6][lm] = tf32r(av1.z); As[nxt][lk + 7][lm] = tf32r(av1.w);
            *reinterpret_cast<float4*>(&Bs[nxt][bk][bn]) =
                make_float4(tf32r(bv.x), tf32r(bv.y), tf32r(bv.z), tf32r(bv.w));
        }
        __syncthreads();
    }

    #pragma unroll
    for (int i = 0; i < 2; i++) {
        int row0 = rowBase + mw + i * 16 + g;
        #pragma unroll
        for (int j = 0; j < 4; j++) {
            int col = colBase + nw + j * 8 + tk * 2;
            float be0 = be[col], be1 = be[col + 1];
            float2 o0 = make_float2(acc[i][j][0] + be0, acc[i][j][1] + be1);
            float2 o1 = make_float2(acc[i][j][2] + be0, acc[i][j][3] + be1);
            *reinterpret_cast<float2*>(d_att1 + (size_t)row0 * ATT + col) = o0;
            *reinterpret_cast<float2*>(d_att1 + (size_t)(row0 + 8) * ATT + col) = o1;
        }
    }
}

// ---------------- batched preds: tf32 MMA, compact rows @ Wfc ----------------
__global__ void __launch_bounds__(256, 2) k_preds_mma(const float* __restrict__ Wfc,
                                                      const float* __restrict__ bfc,
                                                      float* __restrict__ out) {
    int total = d_total;
    int rowBase = blockIdx.x * 128;
    if (rowBase >= total) return;
    int colBase = blockIdx.y * 64;

    __shared__ float As[2][16][136];
    __shared__ float Bs[2][16][72];
    int tid = threadIdx.x;
    int warp = tid >> 5, lane = tid & 31;
    int g = lane >> 2, tk = lane & 3;
    int mw = (warp & 3) * 32, nw = (warp >> 2) * 32;

    int lm = tid >> 1, lk = (tid & 1) << 3;
    int r = rowBase + lm;
    bool rvalid = (r < total);
    const float* Arow = d_hhist + (size_t)(rvalid ? d_rowmap[r] : 0) * DEC;
    int bk = tid >> 4, bn = (tid & 15) << 2;
    int bcol = colBase + bn;
    bool cvalid = (bcol < VV);

    float acc[2][4][4];
    #pragma unroll
    for (int i = 0; i < 2; i++)
        #pragma unroll
        for (int j = 0; j < 4; j++)
            #pragma unroll
            for (int q = 0; q < 4; q++) acc[i][j][q] = 0.f;

    float4 av0, av1, bv;
    auto loadA = [&](int k0) {
        if (rvalid) {
            av0 = *reinterpret_cast<const float4*>(Arow + k0 + lk);
            av1 = *reinterpret_cast<const float4*>(Arow + k0 + lk + 4);
        } else {
            av0 = make_float4(0.f, 0.f, 0.f, 0.f);
            av1 = av0;
        }
    };
    auto loadB = [&](int k0) {
        if (cvalid) bv = *reinterpret_cast<const float4*>(Wfc + (size_t)(k0 + bk) * VV + bcol);
        else        bv = make_float4(0.f, 0.f, 0.f, 0.f);
    };

    loadA(0); loadB(0);
    As[0][lk + 0][lm] = tf32r(av0.x); As[0][lk + 1][lm] = tf32r(av0.y);
    As[0][lk + 2][lm] = tf32r(av0.z); As[0][lk + 3][lm] = tf32r(av0.w);
    As[0][lk + 4][lm] = tf32r(av1.x); As[0][lk + 5][lm] = tf32r(av1.y);
    As[0][lk + 6][lm] = tf32r(av1.z); As[0][lk + 7][lm] = tf32r(av1.w);
    *reinterpret_cast<float4*>(&Bs[0][bk][bn]) =
        make_float4(tf32r(bv.x), tf32r(bv.y), tf32r(bv.z), tf32r(bv.w));
    __syncthreads();

    const int ntiles = DEC / 16;  // 32
    for (int it = 0; it < ntiles; it++) {
        int cur = it & 1;
        bool more = (it + 1 < ntiles);
        if (more) { loadA((it + 1) * 16); loadB((it + 1) * 16); }
        #pragma unroll
        for (int ks = 0; ks < 16; ks += 8) {
            uint32_t a[2][4], bfr[4][2];
            #pragma unroll
            for (int i = 0; i < 2; i++) {
                a[i][0] = __float_as_uint(As[cur][ks + tk][mw + i * 16 + g]);
                a[i][1] = __float_as_uint(As[cur][ks + tk][mw + i * 16 + g + 8]);
                a[i][2] = __float_as_uint(As[cur][ks + tk + 4][mw + i * 16 + g]);
                a[i][3] = __float_as_uint(As[cur][ks + tk + 4][mw + i * 16 + g + 8]);
            }
            #pragma unroll
            for (int j = 0; j < 4; j++) {
                bfr[j][0] = __float_as_uint(Bs[cur][ks + tk][nw + j * 8 + g]);
                bfr[j][1] = __float_as_uint(Bs[cur][ks + tk + 4][nw + j * 8 + g]);
            }
            #pragma unroll
            for (int i = 0; i < 2; i++)
                #pragma unroll
                for (int j = 0; j < 4; j++)
                    mma_tf32(acc[i][j], a[i], bfr[j]);
        }
        if (more) {
            int nxt = cur ^ 1;
            As[nxt][lk + 0][lm] = tf32r(av0.x); As[nxt][lk + 1][lm] = tf32r(av0.y);
            As[nxt][lk + 2][lm] = tf32r(av0.z); As[nxt][lk + 3][lm] = tf32r(av0.w);
            As[nxt][lk + 4][lm] = tf32r(av1.x); As[nxt][lk + 5][lm] = tf32r(av1.y);
            As[nxt][lk + 6][lm] = tf32r(av1.z); As[nxt][lk + 7][lm] = tf32r(av1.w);
            *reinterpret_cast<float4*>(&Bs[nxt][bk][bn]) =
                make_float4(tf32r(bv.x), tf32r(bv.y), tf32r(bv.z), tf32r(bv.w));
        }
        __syncthreads();
    }

    #pragma unroll
    for (int i = 0; i < 2; i++) {
        #pragma unroll
        for (int j = 0; j < 4; j++) {
            int col = colBase + nw + j * 8 + tk * 2;
            if (col >= VV) continue;
            float bf0 = bfc[col], bf1 = bfc[col + 1];
            #pragma unroll
            for (int h = 0; h < 2; h++) {
                int rr = rowBase + mw + i * 16 + g + h * 8;
                if (rr < total) {
                    int mapped = d_rowmap[rr];
                    int t = mapped >> 6, b = mapped & 63;
                    float* orow = out + ((size_t)b * TT + t) * VV;
                    orow[col]     = acc[i][j][h * 2]     + bf0;
                    orow[col + 1] = acc[i][j][h * 2 + 1] + bf1;
                }
            }
        }
    }
}

// ---------------- fused: e -> softmax -> awe -> xbuf, 512 threads, 1 block/b ----------------
__global__ void __launch_bounds__(512, 2) k_attend(
        const float* __restrict__ enc, const int* __restrict__ caps,
        const float* __restrict__ emb,
        const float* __restrict__ Wf, const float* __restrict__ bf,
        float* __restrict__ out_alphas, int t) {
    int b = blockIdx.x;
    if (b >= d_nb[t]) return;
    __shared__ __align__(16) float a2[ATT];
    __shared__ __align__(16) float wf[ATT];
    __shared__ float es[PP];
    __shared__ float red[16];
    __shared__ float redsum[16];
    int tid = threadIdx.x;
    a2[tid] = d_att2[b * ATT + tid];
    wf[tid] = Wf[tid];
    __syncthreads();
    int lane = tid & 31, warp = tid >> 5;

    const float4* a24 = reinterpret_cast<const float4*>(a2);
    const float4* wf4 = reinterpret_cast<const float4*>(wf);
    for (int p = warp; p < PP; p += 16) {
        const float4* row4 = reinterpret_cast<const float4*>(d_att1 + ((size_t)b * PP + p) * ATT);
        float s = 0.f;
        #pragma unroll
        for (int i = 0; i < 4; i++) {
            int idx = lane + i * 32;
            float4 v = row4[idx];
            float4 a = a24[idx];
            float4 w = wf4[idx];
            s += fmaxf(v.x + a.x, 0.f) * w.x;
            s += fmaxf(v.y + a.y, 0.f) * w.y;
            s += fmaxf(v.z + a.z, 0.f) * w.z;
            s += fmaxf(v.w + a.w, 0.f) * w.w;
        }
        #pragma unroll
        for (int off = 16; off > 0; off >>= 1) s += __shfl_xor_sync(0xffffffffu, s, off);
        if (lane == 0) es[p] = s + bf[0];
    }
    __syncthreads();

    float v = (tid < PP) ? es[tid] : -1e30f;
    float m = v;
    #pragma unroll
    for (int off = 16; off > 0; off >>= 1) m = fmaxf(m, __shfl_xor_sync(0xffffffffu, m, off));
    if (lane == 0) red[warp] = m;
    __syncthreads();
    if (tid == 0) {
        float mm = red[0];
        for (int i = 1; i < 16; i++) mm = fmaxf(mm, red[i]);
        red[0] = mm;
    }
    __syncthreads();
    float smax = red[0];
    float ev = (tid < PP) ? __expf(v - smax) : 0.f;
    float s = ev;
    #pragma unroll
    for (int off = 16; off > 0; off >>= 1) s += __shfl_xor_sync(0xffffffffu, s, off);
    if (lane == 0) redsum[warp] = s;
    __syncthreads();
    if (tid == 0) {
        float ss = redsum[0];
        for (int i = 1; i < 16; i++) ss += redsum[i];
        redsum[0] = ss;
    }
    __syncthreads();
    float inv = 1.0f / redsum[0];
    float al = ev * inv;
    if (tid < PP) {
        es[tid] = al;
        out_alphas[((size_t)b * TT + t) * PP + tid] = al;
    }
    __syncthreads();

    int src = d_sort_src[b];
    const float4* enc4 = reinterpret_cast<const float4*>(enc + (size_t)src * PP * EE);
    float4 acc = make_float4(0.f, 0.f, 0.f, 0.f);
    #pragma unroll 4
    for (int p = 0; p < PP; p++) {
        float alp = es[p];
        float4 e4 = enc4[p * 512 + tid];
        acc.x += alp * e4.x; acc.y += alp * e4.y;
        acc.z += alp * e4.z; acc.w += alp * e4.w;
    }
    float4 g4 = reinterpret_cast<const float4*>(d_gate + (size_t)b * EE)[tid];
    float4 o4 = make_float4(acc.x * g4.x, acc.y * g4.y, acc.z * g4.z, acc.w * g4.w);
    float4* xb4 = reinterpret_cast<float4*>(d_xbuf + (size_t)b * 3072);
    xb4[128 + tid] = o4;

    if (tid < 128) {
        int cap = caps[src * LL + t];
        const float4* emb4 = reinterpret_cast<const float4*>(emb + (size_t)cap * EMB);
        xb4[tid] = emb4[tid];
        xb4[640 + tid] = reinterpret_cast<const float4*>(d_h + (size_t)b * DEC)[tid];
    }
}

// ---------------- host launch ----------------
extern "C" void kernel_launch(void* const* d_in, const int* in_sizes, int n_in,
                              void* d_out, int out_size) {
    const float* enc  = (const float*)d_in[0];
    const int*   caps = (const int*)d_in[1];
    const int*   clen = (const int*)d_in[2];
    const float* emb  = (const float*)d_in[3];
    const float* We   = (const float*)d_in[4];
    const float* be   = (const float*)d_in[5];
    const float* Wd   = (const float*)d_in[6];
    const float* bd   = (const float*)d_in[7];
    const float* Wf   = (const float*)d_in[8];
    const float* bf   = (const float*)d_in[9];
    const float* Wih  = (const float*)d_in[10];
    const float* bih  = (const float*)d_in[11];
    const float* Whh  = (const float*)d_in[12];
    const float* bhh  = (const float*)d_in[13];
    const float* Wb   = (const float*)d_in[14];
    const float* bb   = (const float*)d_in[15];
    const float* Whi  = (const float*)d_in[16];
    const float* bhi  = (const float*)d_in[17];
    const float* Wci  = (const float*)d_in[18];
    const float* bci  = (const float*)d_in[19];
    const float* Wfc  = (const float*)d_in[20];
    const float* bfc  = (const float*)d_in[21];
    float* out = (float*)d_out;
    float* out_alphas = out + (size_t)BB * TT * VV;

    k_setup<<<1, 64>>>(clen);
    k_zero<<<2048, 256>>>(out, (size_t)out_size);
    k_mean<<<dim3(8, BB), 256>>>(enc);

    // h0 / c0 (split-K 8 over K=2048)
    k_gemm<<<dim3(16, 8), 256>>>(BUF_MEAN, Whi, nullptr, EE, EE, DEC, -1, 8);
    k_reduce<<<128, 256>>>(DEC, 8, bhi, BUF_H, -1);
    k_gemm<<<dim3(16, 8), 256>>>(BUF_MEAN, Wci, nullptr, EE, EE, DEC, -1, 8);
    k_reduce<<<128, 256>>>(DEC, 8, bci, BUF_C, -1);

    // att1 via tf32 tensor cores
    k_att1_mma<<<dim3(98, 8), 256>>>(enc, We, be);

    for (int t = 0; t < TT; t++) {
        k_ag<<<80, 256>>>(Wd, bd, Wb, bb, t);
        k_attend<<<BB, 512>>>(enc, caps, emb, Wf, bf, out_alphas, t);
        k_gemm<<<dim3(64, 4), 256>>>(BUF_XBUF, Wih, Whh, 3072, 2560, 2048, t, 4);
        k_reduce_lstm<<<128, 256>>>(bih, bhh, t);
    }

    // batched vocab projection via tf32 tensor cores
    k_preds_mma<<<dim3(16, 157), 256>>>(Wfc, bfc, out);
}